// round 1
// baseline (speedup 1.0000x reference)
#include <cuda_runtime.h>
#include <math.h>

// Problem constants (fixed by the dataset)
#define NMAX 100000
#define CH   128        // heads*feat for both layers
#define HEADS 4
#define FEAT 32
#define GMAX 512
#define NEG_SLOPE 0.2f
#define BN_EPS 1e-5f

// ---------------- device scratch (no allocs allowed) ----------------
__device__ float g_h  [NMAX * CH];   // GEMM output h = x @ W  (per layer)
__device__ float g_acc[NMAX * CH];   // attention accumulator / layer activations
__device__ float g_es [NMAX * HEADS];
__device__ float g_ed [NMAX * HEADS];
__device__ float g_m  [NMAX * HEADS];
__device__ float g_den[NMAX * HEADS];
__device__ float g_z  [NMAX * FEAT]; // layer2 per-node output (32 ch)
__device__ float g_bnsum1[CH];
__device__ float g_bnsq1 [CH];
__device__ float g_bnsum2[FEAT];
__device__ float g_bnsq2 [FEAT];
__device__ float g_pool[GMAX * FEAT];
__device__ float g_cnt [GMAX];

// ---------------- helpers ----------------
__device__ __forceinline__ float lrelu(float x) { return x >= 0.f ? x : NEG_SLOPE * x; }
__device__ __forceinline__ float elu_f(float x) { return x > 0.f ? x : expm1f(x); }

__device__ __forceinline__ void atomicMaxF(float* addr, float v) {
    if (v >= 0.f) atomicMax((int*)addr, __float_as_int(v));
    else          atomicMin((unsigned int*)addr, (unsigned int)__float_as_int(v));
}

__device__ __forceinline__ void red_add_v4(float* p, float4 v) {
    asm volatile("red.global.add.v4.f32 [%0], {%1,%2,%3,%4};"
                 :: "l"(p), "f"(v.x), "f"(v.y), "f"(v.z), "f"(v.w) : "memory");
}

// ---------------- kernels ----------------

// zero the accumulators that are atomically updated later
__global__ void k_zero() {
    int i = blockIdx.x * blockDim.x + threadIdx.x;
    if (i < GMAX * FEAT) g_pool[i] = 0.f;
    if (i < GMAX)        g_cnt[i] = 0.f;
    if (i < CH)   { g_bnsum1[i] = 0.f; g_bnsq1[i] = 0.f; }
    if (i < FEAT) { g_bnsum2[i] = 0.f; g_bnsq2[i] = 0.f; }
}

// Y[n,128] = X[n,128] @ W[128,128].  Block = 128 thr, 4 rows/block.
__global__ void k_gemm128(const float* __restrict__ X, const float* __restrict__ W,
                          float* __restrict__ Y, int n) {
    __shared__ float xs[4][128];
    int t = threadIdx.x;
    int rb = blockIdx.x * 4;
#pragma unroll
    for (int r = 0; r < 4; r++) {
        int row = rb + r;
        xs[r][t] = (row < n) ? X[row * CH + t] : 0.f;
    }
    __syncthreads();
    int lr = t >> 5;            // local row 0..3
    int cg = (t & 31) * 4;      // col start
    int row = rb + lr;
    if (row >= n) return;
    float4 acc = make_float4(0.f, 0.f, 0.f, 0.f);
#pragma unroll 8
    for (int k = 0; k < 128; k++) {
        float xv = xs[lr][k];
        float4 w4 = *(const float4*)&W[k * CH + cg];
        acc.x += xv * w4.x; acc.y += xv * w4.y;
        acc.z += xv * w4.z; acc.w += xv * w4.w;
    }
    *(float4*)&Y[row * CH + cg] = acc;
}

// per-node: es/ed = <h[n,h,:], a_src/dst[h,:]> ; m init = self-loop score
__global__ void k_node_prep(const float* __restrict__ h,
                            const float* __restrict__ a_src, const float* __restrict__ a_dst,
                            int n) {
    int i = blockIdx.x * blockDim.x + threadIdx.x;
    if (i >= n) return;
    const float4* hp = (const float4*)&h[(long)i * CH];
    float s[HEADS] = {0,0,0,0}, d[HEADS] = {0,0,0,0};
#pragma unroll
    for (int c = 0; c < 32; c++) {
        float4 hv = hp[c];
        int hh = c >> 3;
        int f = (c & 7) * 4;
        const float* as = &a_src[hh * FEAT + f];
        const float* ad = &a_dst[hh * FEAT + f];
        s[hh] += hv.x * as[0] + hv.y * as[1] + hv.z * as[2] + hv.w * as[3];
        d[hh] += hv.x * ad[0] + hv.y * ad[1] + hv.z * ad[2] + hv.w * ad[3];
    }
#pragma unroll
    for (int hh = 0; hh < HEADS; hh++) {
        g_es[i * HEADS + hh] = s[hh];
        g_ed[i * HEADS + hh] = d[hh];
        g_m [i * HEADS + hh] = lrelu(s[hh] + d[hh]);  // self-loop score
    }
}

// per-edge: m[dst] = max(m[dst], leaky(es[src]+ed[dst]))
__global__ void k_edge_max(const int* __restrict__ src, const int* __restrict__ dst, int E) {
    int e = blockIdx.x * blockDim.x + threadIdx.x;
    if (e >= E) return;
    int s = src[e], d = dst[e];
    float4 es4 = *(const float4*)&g_es[s * HEADS];
    float4 ed4 = *(const float4*)&g_ed[d * HEADS];
    atomicMaxF(&g_m[d * HEADS + 0], lrelu(es4.x + ed4.x));
    atomicMaxF(&g_m[d * HEADS + 1], lrelu(es4.y + ed4.y));
    atomicMaxF(&g_m[d * HEADS + 2], lrelu(es4.z + ed4.z));
    atomicMaxF(&g_m[d * HEADS + 3], lrelu(es4.w + ed4.w));
}

// per-node: initialize den/acc with self-loop contribution (plain stores == zero-init)
__global__ void k_node_self(const float* __restrict__ h, int n) {
    int i = blockIdx.x * blockDim.x + threadIdx.x;
    if (i >= n) return;
    float4 es4 = *(const float4*)&g_es[i * HEADS];
    float4 ed4 = *(const float4*)&g_ed[i * HEADS];
    float4 m4  = *(const float4*)&g_m [i * HEADS];
    float w[HEADS];
    w[0] = expf(lrelu(es4.x + ed4.x) - m4.x);
    w[1] = expf(lrelu(es4.y + ed4.y) - m4.y);
    w[2] = expf(lrelu(es4.z + ed4.z) - m4.z);
    w[3] = expf(lrelu(es4.w + ed4.w) - m4.w);
    *(float4*)&g_den[i * HEADS] = make_float4(w[0], w[1], w[2], w[3]);
    const float4* hp = (const float4*)&h[(long)i * CH];
    float4* ap = (float4*)&g_acc[(long)i * CH];
#pragma unroll
    for (int c = 0; c < 32; c++) {
        float ww = w[c >> 3];
        float4 hv = hp[c];
        ap[c] = make_float4(hv.x * ww, hv.y * ww, hv.z * ww, hv.w * ww);
    }
}

// per-edge: w = exp(e - m[dst]); den[dst]+=w; acc[dst] += w * h[src]
__global__ void k_edge_accum(const int* __restrict__ src, const int* __restrict__ dst,
                             const float* __restrict__ h, int E) {
    int e = blockIdx.x * blockDim.x + threadIdx.x;
    if (e >= E) return;
    int s = src[e], d = dst[e];
    float4 es4 = *(const float4*)&g_es[s * HEADS];
    float4 ed4 = *(const float4*)&g_ed[d * HEADS];
    float4 m4  = *(const float4*)&g_m [d * HEADS];
    float w[HEADS];
    w[0] = expf(lrelu(es4.x + ed4.x) - m4.x);
    w[1] = expf(lrelu(es4.y + ed4.y) - m4.y);
    w[2] = expf(lrelu(es4.z + ed4.z) - m4.z);
    w[3] = expf(lrelu(es4.w + ed4.w) - m4.w);
    red_add_v4(&g_den[d * HEADS], make_float4(w[0], w[1], w[2], w[3]));
    const float4* hp = (const float4*)&h[(long)s * CH];
    float* ap = &g_acc[(long)d * CH];
#pragma unroll
    for (int c = 0; c < 32; c++) {
        float ww = w[c >> 3];
        float4 hv = hp[c];
        red_add_v4(ap + c * 4, make_float4(hv.x * ww, hv.y * ww, hv.z * ww, hv.w * ww));
    }
}

// layer1 finalize: y = acc/den + b1 (in place), accumulate BN stats per channel
__global__ void k_finalize1(const float* __restrict__ b1, int n) {
    int c = threadIdx.x;               // 128 channels
    int r0 = blockIdx.x * 64;
    int r1 = min(r0 + 64, n);
    float b = b1[c];
    float sum = 0.f, sq = 0.f;
    for (int r = r0; r < r1; r++) {
        float v = g_acc[(long)r * CH + c] / g_den[r * HEADS + (c >> 5)] + b;
        g_acc[(long)r * CH + c] = v;
        sum += v; sq += v * v;
    }
    atomicAdd(&g_bnsum1[c], sum);
    atomicAdd(&g_bnsq1[c], sq);
}

// layer1 BN + ELU in place on g_acc
__global__ void k_bn_elu1(const float* __restrict__ gamma, const float* __restrict__ beta,
                          int n, float inv_n) {
    long i = (long)blockIdx.x * blockDim.x + threadIdx.x;
    if (i >= (long)n * CH) return;
    int c = (int)(i & (CH - 1));
    float mean = g_bnsum1[c] * inv_n;
    float var = g_bnsq1[c] * inv_n - mean * mean;
    float rstd = rsqrtf(var + BN_EPS);
    float v = gamma[c] * (g_acc[i] - mean) * rstd + beta[c];
    g_acc[i] = elu_f(v);
}

// layer2 finalize: z[n,f] = mean_h(acc/den) + b2; BN stats over 32 channels
__global__ void k_finalize2(const float* __restrict__ b2, int n) {
    int f = threadIdx.x;               // 32 channels
    int r0 = blockIdx.x * 128;
    int r1 = min(r0 + 128, n);
    float b = b2[f];
    float sum = 0.f, sq = 0.f;
    for (int r = r0; r < r1; r++) {
        float v = 0.f;
#pragma unroll
        for (int hh = 0; hh < HEADS; hh++)
            v += g_acc[(long)r * CH + hh * FEAT + f] / g_den[r * HEADS + hh];
        v = 0.25f * v + b;
        g_z[(long)r * FEAT + f] = v;
        sum += v; sq += v * v;
    }
    atomicAdd(&g_bnsum2[f], sum);
    atomicAdd(&g_bnsq2[f], sq);
}

__global__ void k_bn_elu2(const float* __restrict__ gamma, const float* __restrict__ beta,
                          int n, float inv_n) {
    long i = (long)blockIdx.x * blockDim.x + threadIdx.x;
    if (i >= (long)n * FEAT) return;
    int c = (int)(i & (FEAT - 1));
    float mean = g_bnsum2[c] * inv_n;
    float var = g_bnsq2[c] * inv_n - mean * mean;
    float rstd = rsqrtf(var + BN_EPS);
    float v = gamma[c] * (g_z[i] - mean) * rstd + beta[c];
    g_z[i] = elu_f(v);
}

// segment-sum pool over graphs
__global__ void k_pool(const int* __restrict__ batch, int n) {
    int i = blockIdx.x * blockDim.x + threadIdx.x;
    if (i >= n) return;
    int g = batch[i];
    const float4* zp = (const float4*)&g_z[(long)i * FEAT];
#pragma unroll
    for (int c = 0; c < 8; c++)
        red_add_v4(&g_pool[g * FEAT + c * 4], zp[c]);
    atomicAdd(&g_cnt[g], 1.f);
}

// final: out[g,o] = (pool[g]/max(cnt,1)) @ Wl + bl
__global__ void k_final(const float* __restrict__ Wl, const float* __restrict__ bl,
                        float* __restrict__ out, int G) {
    int idx = blockIdx.x * blockDim.x + threadIdx.x;
    if (idx >= G * 2) return;
    int g = idx >> 1, o = idx & 1;
    float cn = fmaxf(g_cnt[g], 1.f);
    float s = bl[o];
#pragma unroll
    for (int f = 0; f < FEAT; f++)
        s += (g_pool[g * FEAT + f] / cn) * Wl[f * 2 + o];
    out[idx] = s;
}

// ---------------- host launch ----------------
extern "C" void kernel_launch(void* const* d_in, const int* in_sizes, int n_in,
                              void* d_out, int out_size) {
    const float* x   = (const float*)d_in[0];
    const int*   ei  = (const int*)  d_in[1];
    const int*   bat = (const int*)  d_in[2];
    const float* W1  = (const float*)d_in[3];
    const float* as1 = (const float*)d_in[4];
    const float* ad1 = (const float*)d_in[5];
    const float* b1  = (const float*)d_in[6];
    const float* g1  = (const float*)d_in[7];
    const float* be1 = (const float*)d_in[8];
    const float* W2  = (const float*)d_in[9];
    const float* as2 = (const float*)d_in[10];
    const float* ad2 = (const float*)d_in[11];
    const float* b2  = (const float*)d_in[12];
    const float* g2  = (const float*)d_in[13];
    const float* be2 = (const float*)d_in[14];
    const float* Wl  = (const float*)d_in[15];
    const float* bl  = (const float*)d_in[16];
    float* out = (float*)d_out;

    int n = in_sizes[0] / CH;            // 100000
    int E = in_sizes[1] / 2;             // 1600000
    int G = out_size / 2;                // 512
    const int* esrc = ei;
    const int* edst = ei + E;

    static float *ph = nullptr, *pacc = nullptr;
    if (!ph) {
        cudaGetSymbolAddress((void**)&ph,   g_h);
        cudaGetSymbolAddress((void**)&pacc, g_acc);
    }

    float inv_n = 1.f / (float)n;
    int nb_node  = (n + 255) / 256;
    int nb_edge  = (E + 255) / 256;
    int nb_gemm  = (n + 3) / 4;

    k_zero<<<(GMAX * FEAT + 255) / 256, 256>>>();

    // ---- layer 1 ----
    k_gemm128<<<nb_gemm, 128>>>(x, W1, ph, n);
    k_node_prep<<<nb_node, 256>>>(ph, as1, ad1, n);
    k_edge_max<<<nb_edge, 256>>>(esrc, edst, E);
    k_node_self<<<nb_node, 256>>>(ph, n);
    k_edge_accum<<<nb_edge, 256>>>(esrc, edst, ph, E);
    k_finalize1<<<(n + 63) / 64, 128>>>(b1, n);
    k_bn_elu1<<<(int)(((long)n * CH + 255) / 256), 256>>>(g1, be1, n, inv_n);

    // ---- layer 2 ----
    k_gemm128<<<nb_gemm, 128>>>(pacc, W2, ph, n);
    k_node_prep<<<nb_node, 256>>>(ph, as2, ad2, n);
    k_edge_max<<<nb_edge, 256>>>(esrc, edst, E);
    k_node_self<<<nb_node, 256>>>(ph, n);
    k_edge_accum<<<nb_edge, 256>>>(esrc, edst, ph, E);
    k_finalize2<<<(n + 127) / 128, 32>>>(b2, n);
    k_bn_elu2<<<(int)(((long)n * FEAT + 255) / 256), 256>>>(g2, be2, n, inv_n);

    // ---- pool + linear ----
    k_pool<<<nb_node, 256>>>(bat, n);
    k_final<<<(G * 2 + 255) / 256, 256>>>(Wl, bl, out, G);
}

// round 2
// speedup vs baseline: 1.9200x; 1.9200x over previous
#include <cuda_runtime.h>
#include <math.h>

#define NMAX 100000
#define EMAX 1600000
#define CH   128
#define HEADS 4
#define FEAT 32
#define GMAX 512
#define NEG_SLOPE 0.2f
#define BN_EPS 1e-5f
#define SCAN_CHUNK 1024

// ---------------- device scratch ----------------
__device__ float g_h  [NMAX * CH];
__device__ float g_acc[NMAX * CH];
__device__ float g_es [NMAX * HEADS];
__device__ float g_ed [NMAX * HEADS];
__device__ float g_den[NMAX * HEADS];
__device__ float g_z  [NMAX * FEAT];
__device__ float g_bnsum1[CH];
__device__ float g_bnsq1 [CH];
__device__ float g_bnsum2[FEAT];
__device__ float g_bnsq2 [FEAT];
__device__ float g_pool[GMAX * FEAT];
__device__ float g_cnt [GMAX];
// CSR
__device__ int g_deg[NMAX];          // degree, then in-place inclusive chunk scan
__device__ int g_blocksum[128];
__device__ int g_blockoff[128];
__device__ int g_rowptr[NMAX + 1];
__device__ int g_work[NMAX];
__device__ int g_csr[EMAX];

// ---------------- helpers ----------------
__device__ __forceinline__ float lrelu(float x) { return x >= 0.f ? x : NEG_SLOPE * x; }
__device__ __forceinline__ float elu_f(float x) { return x > 0.f ? x : expm1f(x); }

__device__ __forceinline__ void red_add_v4(float* p, float4 v) {
    asm volatile("red.global.add.v4.f32 [%0], {%1,%2,%3,%4};"
                 :: "l"(p), "f"(v.x), "f"(v.y), "f"(v.z), "f"(v.w) : "memory");
}

// ---------------- zero / CSR build ----------------
__global__ void k_zero(int n) {
    int i = blockIdx.x * blockDim.x + threadIdx.x;
    if (i < n)           g_deg[i] = 0;
    if (i < GMAX * FEAT) g_pool[i] = 0.f;
    if (i < GMAX)        g_cnt[i] = 0.f;
    if (i < CH)   { g_bnsum1[i] = 0.f; g_bnsq1[i] = 0.f; }
    if (i < FEAT) { g_bnsum2[i] = 0.f; g_bnsq2[i] = 0.f; }
}

__global__ void k_hist(const int* __restrict__ dst, int E) {
    int e = blockIdx.x * blockDim.x + threadIdx.x;
    if (e < E) atomicAdd(&g_deg[dst[e]], 1);
}

__global__ void k_scan1(int n) {
    __shared__ int s[SCAN_CHUNK];
    int t = threadIdx.x;
    int i = blockIdx.x * SCAN_CHUNK + t;
    int v = (i < n) ? g_deg[i] : 0;
    s[t] = v;
    __syncthreads();
#pragma unroll
    for (int off = 1; off < SCAN_CHUNK; off <<= 1) {
        int u = (t >= off) ? s[t - off] : 0;
        __syncthreads();
        s[t] += u;
        __syncthreads();
    }
    if (i < n) g_deg[i] = s[t];          // inclusive scan within chunk
    if (t == SCAN_CHUNK - 1) g_blocksum[blockIdx.x] = s[t];
}

__global__ void k_scan2(int B) {
    if (threadIdx.x == 0) {
        int run = 0;
        for (int b = 0; b < B; b++) { g_blockoff[b] = run; run += g_blocksum[b]; }
    }
}

__global__ void k_scan3(int n) {
    int i = blockIdx.x * blockDim.x + threadIdx.x;
    if (i > n) return;
    int val = (i == 0) ? 0 : g_deg[i - 1] + g_blockoff[(i - 1) >> 10];
    g_rowptr[i] = val;
    if (i < n) g_work[i] = val;
}

__global__ void k_scatter(const int* __restrict__ src, const int* __restrict__ dst, int E) {
    int e = blockIdx.x * blockDim.x + threadIdx.x;
    if (e >= E) return;
    int d = dst[e];
    int p = atomicAdd(&g_work[d], 1);
    g_csr[p] = src[e];
}

// ---------------- GEMM: Y[n,128] = X[n,128] @ W[128,128] ----------------
// 512 threads, 128 rows per block; W + X tiles in dynamic smem (128 KB).
__global__ void k_gemm_t(const float* __restrict__ X, const float* __restrict__ W,
                         float* __restrict__ Y, int n) {
    extern __shared__ float sm[];
    float* ws = sm;                 // 128*128
    float* xs = sm + 128 * 128;     // 128*128
    int t = threadIdx.x;
    int rb = blockIdx.x * 128;
    float4* ws4 = (float4*)ws;
    float4* xs4 = (float4*)xs;
    const float4* W4 = (const float4*)W;
    const float4* X4 = (const float4*)X;
#pragma unroll
    for (int i = 0; i < 8; i++) {
        int q = i * 512 + t;
        ws4[q] = W4[q];
        int row = q >> 5, cf = q & 31;
        xs4[q] = (rb + row < n) ? X4[(long)(rb + row) * 32 + cf]
                                : make_float4(0.f, 0.f, 0.f, 0.f);
    }
    __syncthreads();
    int cg4 = t & 31;        // float4 column index
    int r0 = (t >> 5) * 8;   // 8 rows per thread
    float4 acc[8];
#pragma unroll
    for (int r = 0; r < 8; r++) acc[r] = make_float4(0.f, 0.f, 0.f, 0.f);
#pragma unroll 4
    for (int k = 0; k < 128; k++) {
        float4 w4 = ws4[k * 32 + cg4];
#pragma unroll
        for (int r = 0; r < 8; r++) {
            float xv = xs[(r0 + r) * 128 + k];
            acc[r].x += xv * w4.x; acc[r].y += xv * w4.y;
            acc[r].z += xv * w4.z; acc[r].w += xv * w4.w;
        }
    }
#pragma unroll
    for (int r = 0; r < 8; r++) {
        int row = rb + r0 + r;
        if (row < n) *(float4*)&Y[(long)row * CH + cg4 * 4] = acc[r];
    }
}

// ---------------- per-node scores ----------------
__global__ void k_node_prep(const float* __restrict__ h,
                            const float* __restrict__ a_src, const float* __restrict__ a_dst,
                            int n) {
    int i = blockIdx.x * blockDim.x + threadIdx.x;
    if (i >= n) return;
    const float4* hp = (const float4*)&h[(long)i * CH];
    float s[HEADS] = {0,0,0,0}, d[HEADS] = {0,0,0,0};
#pragma unroll
    for (int c = 0; c < 32; c++) {
        float4 hv = hp[c];
        int hh = c >> 3;
        int f = (c & 7) * 4;
        const float* as = &a_src[hh * FEAT + f];
        const float* ad = &a_dst[hh * FEAT + f];
        s[hh] += hv.x * as[0] + hv.y * as[1] + hv.z * as[2] + hv.w * as[3];
        d[hh] += hv.x * ad[0] + hv.y * ad[1] + hv.z * ad[2] + hv.w * ad[3];
    }
#pragma unroll
    for (int hh = 0; hh < HEADS; hh++) {
        g_es[i * HEADS + hh] = s[hh];
        g_ed[i * HEADS + hh] = d[hh];
    }
}

// ---------------- warp-per-dst attention (no atomics) ----------------
__global__ void k_attn(const float* __restrict__ h, int n) {
    int warp = (blockIdx.x * blockDim.x + threadIdx.x) >> 5;
    int l = threadIdx.x & 31;
    if (warp >= n) return;
    int d = warp;
    int beg = g_rowptr[d], end = g_rowptr[d + 1];
    float4 ed4 = *(const float4*)&g_ed[d * HEADS];
    float4 esd = *(const float4*)&g_es[d * HEADS];
    // phase A: segment max (self-loop included as init)
    float4 m;
    m.x = lrelu(esd.x + ed4.x); m.y = lrelu(esd.y + ed4.y);
    m.z = lrelu(esd.z + ed4.z); m.w = lrelu(esd.w + ed4.w);
    for (int j = beg + l; j < end; j += 32) {
        int s = g_csr[j];
        float4 es4 = *(const float4*)&g_es[s * HEADS];
        m.x = fmaxf(m.x, lrelu(es4.x + ed4.x));
        m.y = fmaxf(m.y, lrelu(es4.y + ed4.y));
        m.z = fmaxf(m.z, lrelu(es4.z + ed4.z));
        m.w = fmaxf(m.w, lrelu(es4.w + ed4.w));
    }
#pragma unroll
    for (int o = 16; o; o >>= 1) {
        m.x = fmaxf(m.x, __shfl_xor_sync(0xffffffffu, m.x, o));
        m.y = fmaxf(m.y, __shfl_xor_sync(0xffffffffu, m.y, o));
        m.z = fmaxf(m.z, __shfl_xor_sync(0xffffffffu, m.z, o));
        m.w = fmaxf(m.w, __shfl_xor_sync(0xffffffffu, m.w, o));
    }
    // self-loop weight
    float4 wsf;
    wsf.x = expf(lrelu(esd.x + ed4.x) - m.x);
    wsf.y = expf(lrelu(esd.y + ed4.y) - m.y);
    wsf.z = expf(lrelu(esd.z + ed4.z) - m.z);
    wsf.w = expf(lrelu(esd.w + ed4.w) - m.w);
    int hsel = l >> 3;
    int cg = l * 4;
    float wsh = hsel == 0 ? wsf.x : hsel == 1 ? wsf.y : hsel == 2 ? wsf.z : wsf.w;
    float4 acc = *(const float4*)&h[(long)d * CH + cg];
    acc.x *= wsh; acc.y *= wsh; acc.z *= wsh; acc.w *= wsh;
    float4 den = (l == 0) ? wsf : make_float4(0.f, 0.f, 0.f, 0.f);
    // phase B: weights + cooperative gather-accumulate
    for (int j0 = beg; j0 < end; j0 += 32) {
        int j = j0 + l;
        int s = 0;
        float4 w4 = make_float4(0.f, 0.f, 0.f, 0.f);
        if (j < end) {
            s = g_csr[j];
            float4 es4 = *(const float4*)&g_es[s * HEADS];
            w4.x = expf(lrelu(es4.x + ed4.x) - m.x);
            w4.y = expf(lrelu(es4.y + ed4.y) - m.y);
            w4.z = expf(lrelu(es4.z + ed4.z) - m.z);
            w4.w = expf(lrelu(es4.w + ed4.w) - m.w);
        }
        den.x += w4.x; den.y += w4.y; den.z += w4.z; den.w += w4.w;
        int kmax = min(32, end - j0);
        for (int k = 0; k < kmax; k++) {
            int   sk = __shfl_sync(0xffffffffu, s, k);
            float w0 = __shfl_sync(0xffffffffu, w4.x, k);
            float w1 = __shfl_sync(0xffffffffu, w4.y, k);
            float w2 = __shfl_sync(0xffffffffu, w4.z, k);
            float w3 = __shfl_sync(0xffffffffu, w4.w, k);
            float w = hsel == 0 ? w0 : hsel == 1 ? w1 : hsel == 2 ? w2 : w3;
            float4 hv = *(const float4*)&h[(long)sk * CH + cg];
            acc.x += w * hv.x; acc.y += w * hv.y;
            acc.z += w * hv.z; acc.w += w * hv.w;
        }
    }
#pragma unroll
    for (int o = 16; o; o >>= 1) {
        den.x += __shfl_xor_sync(0xffffffffu, den.x, o);
        den.y += __shfl_xor_sync(0xffffffffu, den.y, o);
        den.z += __shfl_xor_sync(0xffffffffu, den.z, o);
        den.w += __shfl_xor_sync(0xffffffffu, den.w, o);
    }
    *(float4*)&g_acc[(long)d * CH + cg] = acc;
    if (l == 0) *(float4*)&g_den[d * HEADS] = den;
}

// ---------------- finalize / BN / pool (unchanged) ----------------
__global__ void k_finalize1(const float* __restrict__ b1, int n) {
    int c = threadIdx.x;
    int r0 = blockIdx.x * 64;
    int r1 = min(r0 + 64, n);
    float b = b1[c];
    float sum = 0.f, sq = 0.f;
    for (int r = r0; r < r1; r++) {
        float v = g_acc[(long)r * CH + c] / g_den[r * HEADS + (c >> 5)] + b;
        g_acc[(long)r * CH + c] = v;
        sum += v; sq += v * v;
    }
    atomicAdd(&g_bnsum1[c], sum);
    atomicAdd(&g_bnsq1[c], sq);
}

__global__ void k_bn_elu1(const float* __restrict__ gamma, const float* __restrict__ beta,
                          int n, float inv_n) {
    long i = (long)blockIdx.x * blockDim.x + threadIdx.x;
    if (i >= (long)n * CH) return;
    int c = (int)(i & (CH - 1));
    float mean = g_bnsum1[c] * inv_n;
    float var = g_bnsq1[c] * inv_n - mean * mean;
    float rstd = rsqrtf(var + BN_EPS);
    float v = gamma[c] * (g_acc[i] - mean) * rstd + beta[c];
    g_acc[i] = elu_f(v);
}

__global__ void k_finalize2(const float* __restrict__ b2, int n) {
    int f = threadIdx.x;
    int r0 = blockIdx.x * 128;
    int r1 = min(r0 + 128, n);
    float b = b2[f];
    float sum = 0.f, sq = 0.f;
    for (int r = r0; r < r1; r++) {
        float v = 0.f;
#pragma unroll
        for (int hh = 0; hh < HEADS; hh++)
            v += g_acc[(long)r * CH + hh * FEAT + f] / g_den[r * HEADS + hh];
        v = 0.25f * v + b;
        g_z[(long)r * FEAT + f] = v;
        sum += v; sq += v * v;
    }
    atomicAdd(&g_bnsum2[f], sum);
    atomicAdd(&g_bnsq2[f], sq);
}

__global__ void k_bn_elu2(const float* __restrict__ gamma, const float* __restrict__ beta,
                          int n, float inv_n) {
    long i = (long)blockIdx.x * blockDim.x + threadIdx.x;
    if (i >= (long)n * FEAT) return;
    int c = (int)(i & (FEAT - 1));
    float mean = g_bnsum2[c] * inv_n;
    float var = g_bnsq2[c] * inv_n - mean * mean;
    float rstd = rsqrtf(var + BN_EPS);
    float v = gamma[c] * (g_z[i] - mean) * rstd + beta[c];
    g_z[i] = elu_f(v);
}

__global__ void k_pool(const int* __restrict__ batch, int n) {
    int i = blockIdx.x * blockDim.x + threadIdx.x;
    if (i >= n) return;
    int g = batch[i];
    const float4* zp = (const float4*)&g_z[(long)i * FEAT];
#pragma unroll
    for (int c = 0; c < 8; c++)
        red_add_v4(&g_pool[g * FEAT + c * 4], zp[c]);
    atomicAdd(&g_cnt[g], 1.f);
}

__global__ void k_final(const float* __restrict__ Wl, const float* __restrict__ bl,
                        float* __restrict__ out, int G) {
    int idx = blockIdx.x * blockDim.x + threadIdx.x;
    if (idx >= G * 2) return;
    int g = idx >> 1, o = idx & 1;
    float cn = fmaxf(g_cnt[g], 1.f);
    float s = bl[o];
#pragma unroll
    for (int f = 0; f < FEAT; f++)
        s += (g_pool[g * FEAT + f] / cn) * Wl[f * 2 + o];
    out[idx] = s;
}

// ---------------- host launch ----------------
extern "C" void kernel_launch(void* const* d_in, const int* in_sizes, int n_in,
                              void* d_out, int out_size) {
    const float* x   = (const float*)d_in[0];
    const int*   ei  = (const int*)  d_in[1];
    const int*   bat = (const int*)  d_in[2];
    const float* W1  = (const float*)d_in[3];
    const float* as1 = (const float*)d_in[4];
    const float* ad1 = (const float*)d_in[5];
    const float* b1  = (const float*)d_in[6];
    const float* g1  = (const float*)d_in[7];
    const float* be1 = (const float*)d_in[8];
    const float* W2  = (const float*)d_in[9];
    const float* as2 = (const float*)d_in[10];
    const float* ad2 = (const float*)d_in[11];
    const float* b2  = (const float*)d_in[12];
    const float* g2  = (const float*)d_in[13];
    const float* be2 = (const float*)d_in[14];
    const float* Wl  = (const float*)d_in[15];
    const float* bl  = (const float*)d_in[16];
    float* out = (float*)d_out;

    int n = in_sizes[0] / CH;   // 100000
    int E = in_sizes[1] / 2;    // 1600000
    int G = out_size / 2;       // 512
    const int* esrc = ei;
    const int* edst = ei + E;

    static float *ph = nullptr, *pacc = nullptr;
    static bool configured = false;
    if (!configured) {
        cudaGetSymbolAddress((void**)&ph,   g_h);
        cudaGetSymbolAddress((void**)&pacc, g_acc);
        cudaFuncSetAttribute(k_gemm_t, cudaFuncAttributeMaxDynamicSharedMemorySize,
                             2 * 128 * 128 * sizeof(float));
        configured = true;
    }

    float inv_n = 1.f / (float)n;
    int nb_node = (n + 255) / 256;
    int nb_edge = (E + 255) / 256;
    int nb_gemm = (n + 127) / 128;
    int nb_attn = (n + 7) / 8;              // 8 warps per 256-thread block
    int B_scan  = (n + SCAN_CHUNK - 1) / SCAN_CHUNK;
    size_t gsmem = 2 * 128 * 128 * sizeof(float);

    // zero + CSR build (shared by both layers)
    k_zero<<<nb_node, 256>>>(n);
    k_hist<<<nb_edge, 256>>>(edst, E);
    k_scan1<<<B_scan, SCAN_CHUNK>>>(n);
    k_scan2<<<1, 32>>>(B_scan);
    k_scan3<<<(n + 256) / 256, 256>>>(n);
    k_scatter<<<nb_edge, 256>>>(esrc, edst, E);

    // ---- layer 1 ----
    k_gemm_t<<<nb_gemm, 512, gsmem>>>(x, W1, ph, n);
    k_node_prep<<<nb_node, 256>>>(ph, as1, ad1, n);
    k_attn<<<nb_attn, 256>>>(ph, n);
    k_finalize1<<<(n + 63) / 64, 128>>>(b1, n);
    k_bn_elu1<<<(int)(((long)n * CH + 255) / 256), 256>>>(g1, be1, n, inv_n);

    // ---- layer 2 ----
    k_gemm_t<<<nb_gemm, 512, gsmem>>>(pacc, W2, ph, n);
    k_node_prep<<<nb_node, 256>>>(ph, as2, ad2, n);
    k_attn<<<nb_attn, 256>>>(ph, n);
    k_finalize2<<<(n + 127) / 128, 32>>>(b2, n);
    k_bn_elu2<<<(int)(((long)n * FEAT + 255) / 256), 256>>>(g2, be2, n, inv_n);

    // ---- pool + linear ----
    k_pool<<<nb_node, 256>>>(bat, n);
    k_final<<<(G * 2 + 255) / 256, 256>>>(Wl, bl, out, G);
}

// round 3
// speedup vs baseline: 2.9679x; 1.5458x over previous
#include <cuda_runtime.h>
#include <math.h>

#define NMAX 100000
#define EMAX 1600000
#define CH   128
#define HEADS 4
#define FEAT 32
#define GMAX 512
#define NEG_SLOPE 0.2f
#define BN_EPS 1e-5f
#define SCAN_CHUNK 1024

// ---------------- device scratch ----------------
__device__ float g_h  [NMAX * CH];
__device__ float g_acc[NMAX * CH];
__device__ float g_es [NMAX * HEADS];
__device__ float g_ed [NMAX * HEADS];
__device__ float g_z  [NMAX * FEAT];
__device__ float g_bnsum1[CH];
__device__ float g_bnsq1 [CH];
__device__ float g_bnsum2[FEAT];
__device__ float g_bnsq2 [FEAT];
__device__ float g_sc1[CH],  g_sh1[CH];
__device__ float g_sc2[FEAT], g_sh2[FEAT];
__device__ float g_pool[GMAX * FEAT];
__device__ float g_cnt [GMAX];
// CSR
__device__ int g_deg[NMAX];
__device__ int g_blocksum[128];
__device__ int g_blockoff[128];
__device__ int g_rowptr[NMAX + 1];
__device__ int g_work[NMAX];
__device__ int g_csr[EMAX];

// ---------------- helpers ----------------
__device__ __forceinline__ float lrelu(float x) { return x >= 0.f ? x : NEG_SLOPE * x; }
__device__ __forceinline__ float elu_f(float x) { return x > 0.f ? x : expm1f(x); }

__device__ __forceinline__ void red_add_v4(float* p, float4 v) {
    asm volatile("red.global.add.v4.f32 [%0], {%1,%2,%3,%4};"
                 :: "l"(p), "f"(v.x), "f"(v.y), "f"(v.z), "f"(v.w) : "memory");
}

// ---------------- zero / CSR build ----------------
__global__ void k_zero(int n) {
    int i = blockIdx.x * blockDim.x + threadIdx.x;
    if (i < n)           g_deg[i] = 0;
    if (i < GMAX * FEAT) g_pool[i] = 0.f;
    if (i < GMAX)        g_cnt[i] = 0.f;
    if (i < CH)   { g_bnsum1[i] = 0.f; g_bnsq1[i] = 0.f; }
    if (i < FEAT) { g_bnsum2[i] = 0.f; g_bnsq2[i] = 0.f; }
}

__global__ void k_hist(const int* __restrict__ dst, int E) {
    int e = blockIdx.x * blockDim.x + threadIdx.x;
    if (e < E) atomicAdd(&g_deg[dst[e]], 1);
}

__global__ void k_scan1(int n) {
    __shared__ int s[SCAN_CHUNK];
    int t = threadIdx.x;
    int i = blockIdx.x * SCAN_CHUNK + t;
    int v = (i < n) ? g_deg[i] : 0;
    s[t] = v;
    __syncthreads();
#pragma unroll
    for (int off = 1; off < SCAN_CHUNK; off <<= 1) {
        int u = (t >= off) ? s[t - off] : 0;
        __syncthreads();
        s[t] += u;
        __syncthreads();
    }
    if (i < n) g_deg[i] = s[t];
    if (t == SCAN_CHUNK - 1) g_blocksum[blockIdx.x] = s[t];
}

__global__ void k_scan2(int B) {
    __shared__ int s[128];
    int t = threadIdx.x;
    int v = (t < B) ? g_blocksum[t] : 0;
    s[t] = v;
    __syncthreads();
#pragma unroll
    for (int off = 1; off < 128; off <<= 1) {
        int u = (t >= off) ? s[t - off] : 0;
        __syncthreads();
        s[t] += u;
        __syncthreads();
    }
    g_blockoff[t] = s[t] - v;   // exclusive
}

__global__ void k_scan3(int n) {
    int i = blockIdx.x * blockDim.x + threadIdx.x;
    if (i > n) return;
    int val = (i == 0) ? 0 : g_deg[i - 1] + g_blockoff[(i - 1) >> 10];
    g_rowptr[i] = val;
    if (i < n) g_work[i] = val;
}

__global__ void k_scatter(const int* __restrict__ src, const int* __restrict__ dst, int E) {
    int e = blockIdx.x * blockDim.x + threadIdx.x;
    if (e >= E) return;
    int d = dst[e];
    int p = atomicAdd(&g_work[d], 1);
    g_csr[p] = src[e];
}

// ---------------- GEMM + fused activation-in + es/ed epilogue ----------------
// Y[n,128] = act(X)[n,128] @ W[128,128]; es/ed = <Y, a_src/a_dst> per head.
// 256 threads, 128 rows/block, 8x8 register tiles, 128KB dynamic smem.
template<bool ACT>
__global__ void __launch_bounds__(256, 1)
k_gemm(const float* __restrict__ X, const float* __restrict__ W,
       const float* __restrict__ sc, const float* __restrict__ sh,
       const float* __restrict__ a_src, const float* __restrict__ a_dst,
       float* __restrict__ Y, int n) {
    extern __shared__ float sm[];
    float4* ws4 = (float4*)sm;                // [128][32] float4
    float4* xs4 = (float4*)(sm + 16384);      // [128][32] float4, row-major
    int t = threadIdx.x;
    int rb = blockIdx.x * 128;
    const float4* W4 = (const float4*)W;
    const float4* X4 = (const float4*)X;
#pragma unroll
    for (int i = 0; i < 16; i++) {
        int q = i * 256 + t;                  // 0..4095
        ws4[q] = W4[q];
        int row = q >> 5, cf = q & 31;
        float4 v = make_float4(0.f, 0.f, 0.f, 0.f);
        if (rb + row < n) v = X4[(long)(rb + row) * 32 + cf];
        if (ACT) {
            int c0 = cf * 4;
            v.x = elu_f(sc[c0 + 0] * v.x + sh[c0 + 0]);
            v.y = elu_f(sc[c0 + 1] * v.y + sh[c0 + 1]);
            v.z = elu_f(sc[c0 + 2] * v.z + sh[c0 + 2]);
            v.w = elu_f(sc[c0 + 3] * v.w + sh[c0 + 3]);
        }
        xs4[q] = v;
    }
    __syncthreads();
    int tx = t & 15, ty = t >> 4;
    int r0 = ty * 8, c0 = tx * 8;
    float acc[8][8];
#pragma unroll
    for (int r = 0; r < 8; r++)
#pragma unroll
        for (int c = 0; c < 8; c++) acc[r][c] = 0.f;

    for (int k4 = 0; k4 < 32; k4++) {
        float4 xv[8];
#pragma unroll
        for (int r = 0; r < 8; r++) xv[r] = xs4[(r0 + r) * 32 + k4];
#pragma unroll
        for (int kk = 0; kk < 4; kk++) {
            float4 w0 = ws4[(k4 * 4 + kk) * 32 + tx * 2];
            float4 w1 = ws4[(k4 * 4 + kk) * 32 + tx * 2 + 1];
#pragma unroll
            for (int r = 0; r < 8; r++) {
                const float* xvf = (const float*)&xv[r];
                float x = xvf[kk];
                acc[r][0] += x * w0.x; acc[r][1] += x * w0.y;
                acc[r][2] += x * w0.z; acc[r][3] += x * w0.w;
                acc[r][4] += x * w1.x; acc[r][5] += x * w1.y;
                acc[r][6] += x * w1.z; acc[r][7] += x * w1.w;
            }
        }
    }
    // epilogue: es/ed per head + store
    int head = tx >> 2;
    int cmod = (tx * 8) & 31;
    float as_[8], ad_[8];
#pragma unroll
    for (int j = 0; j < 8; j++) {
        as_[j] = a_src[head * FEAT + cmod + j];
        ad_[j] = a_dst[head * FEAT + cmod + j];
    }
#pragma unroll
    for (int r = 0; r < 8; r++) {
        float pes = 0.f, ped = 0.f;
#pragma unroll
        for (int j = 0; j < 8; j++) { pes += acc[r][j] * as_[j]; ped += acc[r][j] * ad_[j]; }
        pes += __shfl_xor_sync(0xffffffffu, pes, 1);
        pes += __shfl_xor_sync(0xffffffffu, pes, 2);
        ped += __shfl_xor_sync(0xffffffffu, ped, 1);
        ped += __shfl_xor_sync(0xffffffffu, ped, 2);
        int row = rb + r0 + r;
        if (row < n) {
            if ((tx & 3) == 0) {
                g_es[row * HEADS + head] = pes;
                g_ed[row * HEADS + head] = ped;
            }
            *(float4*)&Y[(long)row * CH + c0]     = make_float4(acc[r][0], acc[r][1], acc[r][2], acc[r][3]);
            *(float4*)&Y[(long)row * CH + c0 + 4] = make_float4(acc[r][4], acc[r][5], acc[r][6], acc[r][7]);
    }
    }
}

// ---------------- persistent warp-per-dst attention + fused finalize ----------------
// LAYER==1: writes g_acc = acc/den + b1 (pre-BN), accumulates stats1.
// LAYER==2: writes g_z = mean_heads(acc/den) + b2, accumulates stats2.
template<int LAYER>
__global__ void __launch_bounds__(256)
k_attn(const float* __restrict__ h, const float* __restrict__ bias,
       float* __restrict__ bnsum, float* __restrict__ bnsq,
       int n, int nwarps) {
    __shared__ int   s_idx[8][32];
    __shared__ float s_w  [8][128];
    int wb = threadIdx.x >> 5, l = threadIdx.x & 31;
    int gw = blockIdx.x * 8 + wb;
    int hsel = l >> 3, cg = l * 4;
    float bs[4] = {0.f, 0.f, 0.f, 0.f};
    float bq[4] = {0.f, 0.f, 0.f, 0.f};

    for (int d = gw; d < n; d += nwarps) {
        int beg = g_rowptr[d], end = g_rowptr[d + 1];
        float4 ed4 = *(const float4*)&g_ed[d * HEADS];
        float4 esd = *(const float4*)&g_es[d * HEADS];
        // self-loop weight (no max subtraction: mathematically identical)
        float4 wsf;
        wsf.x = expf(lrelu(esd.x + ed4.x));
        wsf.y = expf(lrelu(esd.y + ed4.y));
        wsf.z = expf(lrelu(esd.z + ed4.z));
        wsf.w = expf(lrelu(esd.w + ed4.w));
        float wsh = hsel == 0 ? wsf.x : hsel == 1 ? wsf.y : hsel == 2 ? wsf.z : wsf.w;
        float4 acc = *(const float4*)&h[(long)d * CH + cg];
        acc.x *= wsh; acc.y *= wsh; acc.z *= wsh; acc.w *= wsh;
        float4 den = (l == 0) ? wsf : make_float4(0.f, 0.f, 0.f, 0.f);

        for (int j0 = beg; j0 < end; j0 += 32) {
            int j = j0 + l;
            int s = 0;
            float4 w4 = make_float4(0.f, 0.f, 0.f, 0.f);
            if (j < end) {
                s = g_csr[j];
                float4 es4 = *(const float4*)&g_es[s * HEADS];
                w4.x = expf(lrelu(es4.x + ed4.x));
                w4.y = expf(lrelu(es4.y + ed4.y));
                w4.z = expf(lrelu(es4.z + ed4.z));
                w4.w = expf(lrelu(es4.w + ed4.w));
            }
            den.x += w4.x; den.y += w4.y; den.z += w4.z; den.w += w4.w;
            s_idx[wb][l] = s;
            *(float4*)&s_w[wb][l * 4] = w4;
            __syncwarp();
            int kmax = min(32, end - j0);
#pragma unroll 4
            for (int k = 0; k < kmax; k++) {
                int   sk = s_idx[wb][k];
                float w  = s_w[wb][k * 4 + hsel];
                float4 hv = *(const float4*)&h[(long)sk * CH + cg];
                acc.x += w * hv.x; acc.y += w * hv.y;
                acc.z += w * hv.z; acc.w += w * hv.w;
            }
            __syncwarp();
        }
#pragma unroll
        for (int o = 16; o; o >>= 1) {
            den.x += __shfl_xor_sync(0xffffffffu, den.x, o);
            den.y += __shfl_xor_sync(0xffffffffu, den.y, o);
            den.z += __shfl_xor_sync(0xffffffffu, den.z, o);
            den.w += __shfl_xor_sync(0xffffffffu, den.w, o);
        }
        float dh = hsel == 0 ? den.x : hsel == 1 ? den.y : hsel == 2 ? den.z : den.w;
        float rd = 1.f / dh;
        if (LAYER == 1) {
            float4 b4 = *(const float4*)&bias[cg];
            float4 v;
            v.x = acc.x * rd + b4.x; v.y = acc.y * rd + b4.y;
            v.z = acc.z * rd + b4.z; v.w = acc.w * rd + b4.w;
            *(float4*)&g_acc[(long)d * CH + cg] = v;
            bs[0] += v.x; bs[1] += v.y; bs[2] += v.z; bs[3] += v.w;
            bq[0] += v.x * v.x; bq[1] += v.y * v.y; bq[2] += v.z * v.z; bq[3] += v.w * v.w;
        } else {
            float4 v;
            v.x = acc.x * rd; v.y = acc.y * rd; v.z = acc.z * rd; v.w = acc.w * rd;
            // sum over heads: lanes l, l^8, l^16 (, ^24) share f = (l&7)*4+j
#pragma unroll
            for (int o = 8; o <= 16; o <<= 1) {
                v.x += __shfl_xor_sync(0xffffffffu, v.x, o);
                v.y += __shfl_xor_sync(0xffffffffu, v.y, o);
                v.z += __shfl_xor_sync(0xffffffffu, v.z, o);
                v.w += __shfl_xor_sync(0xffffffffu, v.w, o);
            }
            if (l < 8) {
                float4 b4 = *(const float4*)&bias[l * 4];
                v.x = 0.25f * v.x + b4.x; v.y = 0.25f * v.y + b4.y;
                v.z = 0.25f * v.z + b4.z; v.w = 0.25f * v.w + b4.w;
                *(float4*)&g_z[(long)d * FEAT + l * 4] = v;
                bs[0] += v.x; bs[1] += v.y; bs[2] += v.z; bs[3] += v.w;
                bq[0] += v.x * v.x; bq[1] += v.y * v.y; bq[2] += v.z * v.z; bq[3] += v.w * v.w;
            }
        }
    }
    // flush BN stats
    if (LAYER == 1 || l < 8) {
        int c0 = (LAYER == 1) ? cg : l * 4;
#pragma unroll
        for (int j = 0; j < 4; j++) {
            atomicAdd(&bnsum[c0 + j], bs[j]);
            atomicAdd(&bnsq [c0 + j], bq[j]);
        }
    }
}

// ---------------- BN scale/shift prep ----------------
__global__ void k_bnprep(const float* __restrict__ gamma, const float* __restrict__ beta,
                         const float* __restrict__ bnsum, const float* __restrict__ bnsq,
                         float* __restrict__ sc, float* __restrict__ sh,
                         int C, float inv_n) {
    int c = threadIdx.x;
    if (c >= C) return;
    float mean = bnsum[c] * inv_n;
    float var  = bnsq[c] * inv_n - mean * mean;
    float g = gamma[c] * rsqrtf(var + BN_EPS);
    sc[c] = g;
    sh[c] = beta[c] - mean * g;
}

// ---------------- pool with fused BN+ELU ----------------
__global__ void k_pool(const int* __restrict__ batch, int n) {
    int i = blockIdx.x * blockDim.x + threadIdx.x;
    if (i >= n) return;
    int g = batch[i];
    const float4* zp = (const float4*)&g_z[(long)i * FEAT];
#pragma unroll
    for (int c = 0; c < 8; c++) {
        float4 z = zp[c];
        int c0 = c * 4;
        z.x = elu_f(g_sc2[c0 + 0] * z.x + g_sh2[c0 + 0]);
        z.y = elu_f(g_sc2[c0 + 1] * z.y + g_sh2[c0 + 1]);
        z.z = elu_f(g_sc2[c0 + 2] * z.z + g_sh2[c0 + 2]);
        z.w = elu_f(g_sc2[c0 + 3] * z.w + g_sh2[c0 + 3]);
        red_add_v4(&g_pool[g * FEAT + c0], z);
    }
    atomicAdd(&g_cnt[g], 1.f);
}

__global__ void k_final(const float* __restrict__ Wl, const float* __restrict__ bl,
                        float* __restrict__ out, int G) {
    int idx = blockIdx.x * blockDim.x + threadIdx.x;
    if (idx >= G * 2) return;
    int g = idx >> 1, o = idx & 1;
    float cn = fmaxf(g_cnt[g], 1.f);
    float s = bl[o];
#pragma unroll
    for (int f = 0; f < FEAT; f++)
        s += (g_pool[g * FEAT + f] / cn) * Wl[f * 2 + o];
    out[idx] = s;
}

// ---------------- host launch ----------------
extern "C" void kernel_launch(void* const* d_in, const int* in_sizes, int n_in,
                              void* d_out, int out_size) {
    const float* x   = (const float*)d_in[0];
    const int*   ei  = (const int*)  d_in[1];
    const int*   bat = (const int*)  d_in[2];
    const float* W1  = (const float*)d_in[3];
    const float* as1 = (const float*)d_in[4];
    const float* ad1 = (const float*)d_in[5];
    const float* b1  = (const float*)d_in[6];
    const float* g1  = (const float*)d_in[7];
    const float* be1 = (const float*)d_in[8];
    const float* W2  = (const float*)d_in[9];
    const float* as2 = (const float*)d_in[10];
    const float* ad2 = (const float*)d_in[11];
    const float* b2  = (const float*)d_in[12];
    const float* g2  = (const float*)d_in[13];
    const float* be2 = (const float*)d_in[14];
    const float* Wl  = (const float*)d_in[15];
    const float* bl  = (const float*)d_in[16];
    float* out = (float*)d_out;

    int n = in_sizes[0] / CH;   // 100000
    int E = in_sizes[1] / 2;    // 1600000
    int G = out_size / 2;       // 512
    const int* esrc = ei;
    const int* edst = ei + E;

    static float *ph = nullptr, *pacc = nullptr;
    static float *psc1, *psh1, *psc2, *psh2;
    static float *pbs1, *pbq1, *pbs2, *pbq2;
    static bool configured = false;
    if (!configured) {
        cudaGetSymbolAddress((void**)&ph,   g_h);
        cudaGetSymbolAddress((void**)&pacc, g_acc);
        cudaGetSymbolAddress((void**)&psc1, g_sc1);
        cudaGetSymbolAddress((void**)&psh1, g_sh1);
        cudaGetSymbolAddress((void**)&psc2, g_sc2);
        cudaGetSymbolAddress((void**)&psh2, g_sh2);
        cudaGetSymbolAddress((void**)&pbs1, g_bnsum1);
        cudaGetSymbolAddress((void**)&pbq1, g_bnsq1);
        cudaGetSymbolAddress((void**)&pbs2, g_bnsum2);
        cudaGetSymbolAddress((void**)&pbq2, g_bnsq2);
        cudaFuncSetAttribute(k_gemm<false>, cudaFuncAttributeMaxDynamicSharedMemorySize,
                             2 * 128 * 128 * sizeof(float));
        cudaFuncSetAttribute(k_gemm<true>, cudaFuncAttributeMaxDynamicSharedMemorySize,
                             2 * 128 * 128 * sizeof(float));
        configured = true;
    }

    float inv_n = 1.f / (float)n;
    int nb_node = (n + 255) / 256;
    int nb_edge = (E + 255) / 256;
    int nb_gemm = (n + 127) / 128;
    int nb_attn = 592;                       // 4 blocks/SM x 148
    int nwarps  = nb_attn * 8;
    int B_scan  = (n + SCAN_CHUNK - 1) / SCAN_CHUNK;
    size_t gsmem = 2 * 128 * 128 * sizeof(float);

    // zero + CSR build
    k_zero<<<nb_node, 256>>>(n);
    k_hist<<<nb_edge, 256>>>(edst, E);
    k_scan1<<<B_scan, SCAN_CHUNK>>>(n);
    k_scan2<<<1, 128>>>(B_scan);
    k_scan3<<<(n + 256) / 256, 256>>>(n);
    k_scatter<<<nb_edge, 256>>>(esrc, edst, E);

    // ---- layer 1 ----
    k_gemm<false><<<nb_gemm, 256, gsmem>>>(x, W1, nullptr, nullptr, as1, ad1, ph, n);
    k_attn<1><<<nb_attn, 256>>>(ph, b1, pbs1, pbq1, n, nwarps);
    k_bnprep<<<1, CH>>>(g1, be1, pbs1, pbq1, psc1, psh1, CH, inv_n);

    // ---- layer 2 (BN+ELU of layer1 fused into GEMM load) ----
    k_gemm<true><<<nb_gemm, 256, gsmem>>>(pacc, W2, psc1, psh1, as2, ad2, ph, n);
    k_attn<2><<<nb_attn, 256>>>(ph, b2, pbs2, pbq2, n, nwarps);
    k_bnprep<<<1, FEAT>>>(g2, be2, pbs2, pbq2, psc2, psh2, FEAT, inv_n);

    // ---- pool (BN+ELU fused) + linear ----
    k_pool<<<nb_node, 256>>>(bat, n);
    k_final<<<(G * 2 + 255) / 256, 256>>>(Wl, bl, out, G);
}

// round 4
// speedup vs baseline: 3.2089x; 1.0812x over previous
#include <cuda_runtime.h>
#include <cuda_fp16.h>
#include <math.h>

#define NMAX 100000
#define EMAX 1600000
#define CH   128
#define HEADS 4
#define FEAT 32
#define GMAX 512
#define NEG_SLOPE 0.2f
#define BN_EPS 1e-5f
#define SCAN_CHUNK 1024

// ---------------- device scratch ----------------
__device__ __half g_hh[NMAX * CH];   // GEMM output h (fp16) — attention payload
__device__ float g_acc[NMAX * CH];   // layer1 activations (fp32, pre-BN)
__device__ float g_es [NMAX * HEADS];
__device__ float g_ed [NMAX * HEADS];
__device__ float g_z  [NMAX * FEAT];
__device__ float g_bnsum1[CH];
__device__ float g_bnsq1 [CH];
__device__ float g_bnsum2[FEAT];
__device__ float g_bnsq2 [FEAT];
__device__ float g_sc1[CH],  g_sh1[CH];
__device__ float g_sc2[FEAT], g_sh2[FEAT];
__device__ float g_pool[GMAX * FEAT];
__device__ float g_cnt [GMAX];
// CSR
__device__ int g_deg[NMAX];
__device__ int g_blocksum[128];
__device__ int g_blockoff[128];
__device__ int g_rowptr[NMAX + 1];
__device__ int g_work[NMAX];
__device__ int g_csr[EMAX];

// ---------------- helpers ----------------
__device__ __forceinline__ float lrelu(float x) { return x >= 0.f ? x : NEG_SLOPE * x; }
__device__ __forceinline__ float elu_f(float x) { return x > 0.f ? x : expm1f(x); }

__device__ __forceinline__ void red_add_v4(float* p, float4 v) {
    asm volatile("red.global.add.v4.f32 [%0], {%1,%2,%3,%4};"
                 :: "l"(p), "f"(v.x), "f"(v.y), "f"(v.z), "f"(v.w) : "memory");
}

// load 4 consecutive halfs as float4 (8B load)
__device__ __forceinline__ float4 ld_h4(const __half* p) {
    uint2 raw = *(const uint2*)p;
    float2 fa = __half22float2(*(__half2*)&raw.x);
    float2 fb = __half22float2(*(__half2*)&raw.y);
    return make_float4(fa.x, fa.y, fb.x, fb.y);
}

// ---------------- zero / CSR build ----------------
__global__ void k_zero(int n) {
    int i = blockIdx.x * blockDim.x + threadIdx.x;
    if (i < n)           g_deg[i] = 0;
    if (i < GMAX * FEAT) g_pool[i] = 0.f;
    if (i < GMAX)        g_cnt[i] = 0.f;
    if (i < CH)   { g_bnsum1[i] = 0.f; g_bnsq1[i] = 0.f; }
    if (i < FEAT) { g_bnsum2[i] = 0.f; g_bnsq2[i] = 0.f; }
}

__global__ void k_hist(const int* __restrict__ dst, int E) {
    int e = blockIdx.x * blockDim.x + threadIdx.x;
    if (e < E) atomicAdd(&g_deg[dst[e]], 1);
}

// hierarchical warp-shuffle inclusive scan over 1024-chunks
__global__ void k_scan1(int n) {
    __shared__ int wsum[32];
    int t = threadIdx.x;
    int i = blockIdx.x * SCAN_CHUNK + t;
    int l = t & 31, w = t >> 5;
    int v = (i < n) ? g_deg[i] : 0;
    int x = v;
#pragma unroll
    for (int off = 1; off < 32; off <<= 1) {
        int u = __shfl_up_sync(0xffffffffu, x, off);
        if (l >= off) x += u;
    }
    if (l == 31) wsum[w] = x;
    __syncthreads();
    if (w == 0) {
        int y = wsum[l];
#pragma unroll
        for (int off = 1; off < 32; off <<= 1) {
            int u = __shfl_up_sync(0xffffffffu, y, off);
            if (l >= off) y += u;
        }
        wsum[l] = y;
    }
    __syncthreads();
    if (w > 0) x += wsum[w - 1];
    if (i < n) g_deg[i] = x;
    if (t == SCAN_CHUNK - 1) g_blocksum[blockIdx.x] = x;
}

__global__ void k_scan2(int B) {
    __shared__ int s[128];
    int t = threadIdx.x;
    int v = (t < B) ? g_blocksum[t] : 0;
    s[t] = v;
    __syncthreads();
#pragma unroll
    for (int off = 1; off < 128; off <<= 1) {
        int u = (t >= off) ? s[t - off] : 0;
        __syncthreads();
        s[t] += u;
        __syncthreads();
    }
    g_blockoff[t] = s[t] - v;   // exclusive
}

__global__ void k_scan3(int n) {
    int i = blockIdx.x * blockDim.x + threadIdx.x;
    if (i > n) return;
    int val = (i == 0) ? 0 : g_deg[i - 1] + g_blockoff[(i - 1) >> 10];
    g_rowptr[i] = val;
    if (i < n) g_work[i] = val;
}

__global__ void k_scatter(const int* __restrict__ src, const int* __restrict__ dst, int E) {
    int e = blockIdx.x * blockDim.x + threadIdx.x;
    if (e >= E) return;
    int d = dst[e];
    int p = atomicAdd(&g_work[d], 1);
    g_csr[p] = src[e];
}

// ---------------- GEMM + fused act-in + es/ed epilogue; fp16 h out ----------------
template<bool ACT>
__global__ void __launch_bounds__(256, 1)
k_gemm(const float* __restrict__ X, const float* __restrict__ W,
       const float* __restrict__ sc, const float* __restrict__ sh,
       const float* __restrict__ a_src, const float* __restrict__ a_dst,
       __half* __restrict__ Y, int n) {
    extern __shared__ float sm[];
    float4* ws4 = (float4*)sm;                // [128][32] float4
    float4* xs4 = (float4*)(sm + 16384);      // [128][32] float4
    int t = threadIdx.x;
    int rb = blockIdx.x * 128;
    const float4* W4 = (const float4*)W;
    const float4* X4 = (const float4*)X;
#pragma unroll
    for (int i = 0; i < 16; i++) {
        int q = i * 256 + t;
        ws4[q] = W4[q];
        int row = q >> 5, cf = q & 31;
        float4 v = make_float4(0.f, 0.f, 0.f, 0.f);
        if (rb + row < n) v = X4[(long)(rb + row) * 32 + cf];
        if (ACT) {
            int c0 = cf * 4;
            v.x = elu_f(sc[c0 + 0] * v.x + sh[c0 + 0]);
            v.y = elu_f(sc[c0 + 1] * v.y + sh[c0 + 1]);
            v.z = elu_f(sc[c0 + 2] * v.z + sh[c0 + 2]);
            v.w = elu_f(sc[c0 + 3] * v.w + sh[c0 + 3]);
        }
        xs4[q] = v;
    }
    __syncthreads();
    int tx = t & 15, ty = t >> 4;
    int r0 = ty * 8, c0 = tx * 8;
    float acc[8][8];
#pragma unroll
    for (int r = 0; r < 8; r++)
#pragma unroll
        for (int c = 0; c < 8; c++) acc[r][c] = 0.f;

    for (int k4 = 0; k4 < 32; k4++) {
        float4 xv[8];
#pragma unroll
        for (int r = 0; r < 8; r++) xv[r] = xs4[(r0 + r) * 32 + k4];
#pragma unroll
        for (int kk = 0; kk < 4; kk++) {
            float4 w0 = ws4[(k4 * 4 + kk) * 32 + tx * 2];
            float4 w1 = ws4[(k4 * 4 + kk) * 32 + tx * 2 + 1];
#pragma unroll
            for (int r = 0; r < 8; r++) {
                const float* xvf = (const float*)&xv[r];
                float x = xvf[kk];
                acc[r][0] += x * w0.x; acc[r][1] += x * w0.y;
                acc[r][2] += x * w0.z; acc[r][3] += x * w0.w;
                acc[r][4] += x * w1.x; acc[r][5] += x * w1.y;
                acc[r][6] += x * w1.z; acc[r][7] += x * w1.w;
            }
        }
    }
    // epilogue: es/ed per head (fp32 accumulators) + fp16 store
    int head = tx >> 2;
    int cmod = (tx * 8) & 31;
    float as_[8], ad_[8];
#pragma unroll
    for (int j = 0; j < 8; j++) {
        as_[j] = a_src[head * FEAT + cmod + j];
        ad_[j] = a_dst[head * FEAT + cmod + j];
    }
#pragma unroll
    for (int r = 0; r < 8; r++) {
        float pes = 0.f, ped = 0.f;
#pragma unroll
        for (int j = 0; j < 8; j++) { pes += acc[r][j] * as_[j]; ped += acc[r][j] * ad_[j]; }
        pes += __shfl_xor_sync(0xffffffffu, pes, 1);
        pes += __shfl_xor_sync(0xffffffffu, pes, 2);
        ped += __shfl_xor_sync(0xffffffffu, ped, 1);
        ped += __shfl_xor_sync(0xffffffffu, ped, 2);
        int row = rb + r0 + r;
        if (row < n) {
            if ((tx & 3) == 0) {
                g_es[row * HEADS + head] = pes;
                g_ed[row * HEADS + head] = ped;
            }
            __half2 h0 = __floats2half2_rn(acc[r][0], acc[r][1]);
            __half2 h1 = __floats2half2_rn(acc[r][2], acc[r][3]);
            __half2 h2 = __floats2half2_rn(acc[r][4], acc[r][5]);
            __half2 h3 = __floats2half2_rn(acc[r][6], acc[r][7]);
            uint4 u;
            u.x = *(unsigned*)&h0; u.y = *(unsigned*)&h1;
            u.z = *(unsigned*)&h2; u.w = *(unsigned*)&h3;
            *(uint4*)&Y[(long)row * CH + c0] = u;
        }
    }
}

// ---------------- persistent warp-per-dst attention + fused finalize ----------------
template<int LAYER>
__global__ void __launch_bounds__(256)
k_attn(const __half* __restrict__ h, const float* __restrict__ bias,
       float* __restrict__ bnsum, float* __restrict__ bnsq,
       int n, int nwarps) {
    __shared__ int   s_idx[8][32];
    __shared__ float s_w  [8][128];
    int wb = threadIdx.x >> 5, l = threadIdx.x & 31;
    int gw = blockIdx.x * 8 + wb;
    int hsel = l >> 3, cg = l * 4;
    float bs[4] = {0.f, 0.f, 0.f, 0.f};
    float bq[4] = {0.f, 0.f, 0.f, 0.f};

    for (int d = gw; d < n; d += nwarps) {
        int beg = g_rowptr[d], end = g_rowptr[d + 1];
        float4 ed4 = *(const float4*)&g_ed[d * HEADS];
        float4 esd = *(const float4*)&g_es[d * HEADS];
        float4 wsf;
        wsf.x = __expf(lrelu(esd.x + ed4.x));
        wsf.y = __expf(lrelu(esd.y + ed4.y));
        wsf.z = __expf(lrelu(esd.z + ed4.z));
        wsf.w = __expf(lrelu(esd.w + ed4.w));
        float wsh = hsel == 0 ? wsf.x : hsel == 1 ? wsf.y : hsel == 2 ? wsf.z : wsf.w;
        float4 acc = ld_h4(&h[(long)d * CH + cg]);
        acc.x *= wsh; acc.y *= wsh; acc.z *= wsh; acc.w *= wsh;
        float4 den = (l == 0) ? wsf : make_float4(0.f, 0.f, 0.f, 0.f);

        for (int j0 = beg; j0 < end; j0 += 32) {
            int j = j0 + l;
            int s = 0;
            float4 w4 = make_float4(0.f, 0.f, 0.f, 0.f);
            if (j < end) {
                s = g_csr[j];
                float4 es4 = *(const float4*)&g_es[s * HEADS];
                w4.x = __expf(lrelu(es4.x + ed4.x));
                w4.y = __expf(lrelu(es4.y + ed4.y));
                w4.z = __expf(lrelu(es4.z + ed4.z));
                w4.w = __expf(lrelu(es4.w + ed4.w));
            }
            den.x += w4.x; den.y += w4.y; den.z += w4.z; den.w += w4.w;
            s_idx[wb][l] = s;
            *(float4*)&s_w[wb][l * 4] = w4;
            __syncwarp();
            int kmax = min(32, end - j0);
#pragma unroll 4
            for (int k = 0; k < kmax; k++) {
                int   sk = s_idx[wb][k];
                float w  = s_w[wb][k * 4 + hsel];
                float4 hv = ld_h4(&h[(long)sk * CH + cg]);
                acc.x += w * hv.x; acc.y += w * hv.y;
                acc.z += w * hv.z; acc.w += w * hv.w;
            }
            __syncwarp();
        }
#pragma unroll
        for (int o = 16; o; o >>= 1) {
            den.x += __shfl_xor_sync(0xffffffffu, den.x, o);
            den.y += __shfl_xor_sync(0xffffffffu, den.y, o);
            den.z += __shfl_xor_sync(0xffffffffu, den.z, o);
            den.w += __shfl_xor_sync(0xffffffffu, den.w, o);
        }
        float dh = hsel == 0 ? den.x : hsel == 1 ? den.y : hsel == 2 ? den.z : den.w;
        float rd = 1.f / dh;
        if (LAYER == 1) {
            float4 b4 = *(const float4*)&bias[cg];
            float4 v;
            v.x = acc.x * rd + b4.x; v.y = acc.y * rd + b4.y;
            v.z = acc.z * rd + b4.z; v.w = acc.w * rd + b4.w;
            *(float4*)&g_acc[(long)d * CH + cg] = v;
            bs[0] += v.x; bs[1] += v.y; bs[2] += v.z; bs[3] += v.w;
            bq[0] += v.x * v.x; bq[1] += v.y * v.y; bq[2] += v.z * v.z; bq[3] += v.w * v.w;
        } else {
            float4 v;
            v.x = acc.x * rd; v.y = acc.y * rd; v.z = acc.z * rd; v.w = acc.w * rd;
#pragma unroll
            for (int o = 8; o <= 16; o <<= 1) {
                v.x += __shfl_xor_sync(0xffffffffu, v.x, o);
                v.y += __shfl_xor_sync(0xffffffffu, v.y, o);
                v.z += __shfl_xor_sync(0xffffffffu, v.z, o);
                v.w += __shfl_xor_sync(0xffffffffu, v.w, o);
            }
            if (l < 8) {
                float4 b4 = *(const float4*)&bias[l * 4];
                v.x = 0.25f * v.x + b4.x; v.y = 0.25f * v.y + b4.y;
                v.z = 0.25f * v.z + b4.z; v.w = 0.25f * v.w + b4.w;
                *(float4*)&g_z[(long)d * FEAT + l * 4] = v;
                bs[0] += v.x; bs[1] += v.y; bs[2] += v.z; bs[3] += v.w;
                bq[0] += v.x * v.x; bq[1] += v.y * v.y; bq[2] += v.z * v.z; bq[3] += v.w * v.w;
            }
        }
    }
    if (LAYER == 1 || l < 8) {
        int c0 = (LAYER == 1) ? cg : l * 4;
#pragma unroll
        for (int j = 0; j < 4; j++) {
            atomicAdd(&bnsum[c0 + j], bs[j]);
            atomicAdd(&bnsq [c0 + j], bq[j]);
        }
    }
}

// ---------------- BN scale/shift prep ----------------
__global__ void k_bnprep(const float* __restrict__ gamma, const float* __restrict__ beta,
                         const float* __restrict__ bnsum, const float* __restrict__ bnsq,
                         float* __restrict__ sc, float* __restrict__ sh,
                         int C, float inv_n) {
    int c = threadIdx.x;
    if (c >= C) return;
    float mean = bnsum[c] * inv_n;
    float var  = bnsq[c] * inv_n - mean * mean;
    float g = gamma[c] * rsqrtf(var + BN_EPS);
    sc[c] = g;
    sh[c] = beta[c] - mean * g;
}

// ---------------- pool with fused BN+ELU ----------------
__global__ void k_pool(const int* __restrict__ batch, int n) {
    int i = blockIdx.x * blockDim.x + threadIdx.x;
    if (i >= n) return;
    int g = batch[i];
    const float4* zp = (const float4*)&g_z[(long)i * FEAT];
#pragma unroll
    for (int c = 0; c < 8; c++) {
        float4 z = zp[c];
        int c0 = c * 4;
        z.x = elu_f(g_sc2[c0 + 0] * z.x + g_sh2[c0 + 0]);
        z.y = elu_f(g_sc2[c0 + 1] * z.y + g_sh2[c0 + 1]);
        z.z = elu_f(g_sc2[c0 + 2] * z.z + g_sh2[c0 + 2]);
        z.w = elu_f(g_sc2[c0 + 3] * z.w + g_sh2[c0 + 3]);
        red_add_v4(&g_pool[g * FEAT + c0], z);
    }
    atomicAdd(&g_cnt[g], 1.f);
}

__global__ void k_final(const float* __restrict__ Wl, const float* __restrict__ bl,
                        float* __restrict__ out, int G) {
    int idx = blockIdx.x * blockDim.x + threadIdx.x;
    if (idx >= G * 2) return;
    int g = idx >> 1, o = idx & 1;
    float cn = fmaxf(g_cnt[g], 1.f);
    float s = bl[o];
#pragma unroll
    for (int f = 0; f < FEAT; f++)
        s += (g_pool[g * FEAT + f] / cn) * Wl[f * 2 + o];
    out[idx] = s;
}

// ---------------- host launch ----------------
extern "C" void kernel_launch(void* const* d_in, const int* in_sizes, int n_in,
                              void* d_out, int out_size) {
    const float* x   = (const float*)d_in[0];
    const int*   ei  = (const int*)  d_in[1];
    const int*   bat = (const int*)  d_in[2];
    const float* W1  = (const float*)d_in[3];
    const float* as1 = (const float*)d_in[4];
    const float* ad1 = (const float*)d_in[5];
    const float* b1  = (const float*)d_in[6];
    const float* g1  = (const float*)d_in[7];
    const float* be1 = (const float*)d_in[8];
    const float* W2  = (const float*)d_in[9];
    const float* as2 = (const float*)d_in[10];
    const float* ad2 = (const float*)d_in[11];
    const float* b2  = (const float*)d_in[12];
    const float* g2  = (const float*)d_in[13];
    const float* be2 = (const float*)d_in[14];
    const float* Wl  = (const float*)d_in[15];
    const float* bl  = (const float*)d_in[16];
    float* out = (float*)d_out;

    int n = in_sizes[0] / CH;   // 100000
    int E = in_sizes[1] / 2;    // 1600000
    int G = out_size / 2;       // 512
    const int* esrc = ei;
    const int* edst = ei + E;

    static __half* phh = nullptr;
    static float *pacc;
    static float *psc1, *psh1, *psc2, *psh2;
    static float *pbs1, *pbq1, *pbs2, *pbq2;
    static bool configured = false;
    if (!configured) {
        cudaGetSymbolAddress((void**)&phh,  g_hh);
        cudaGetSymbolAddress((void**)&pacc, g_acc);
        cudaGetSymbolAddress((void**)&psc1, g_sc1);
        cudaGetSymbolAddress((void**)&psh1, g_sh1);
        cudaGetSymbolAddress((void**)&psc2, g_sc2);
        cudaGetSymbolAddress((void**)&psh2, g_sh2);
        cudaGetSymbolAddress((void**)&pbs1, g_bnsum1);
        cudaGetSymbolAddress((void**)&pbq1, g_bnsq1);
        cudaGetSymbolAddress((void**)&pbs2, g_bnsum2);
        cudaGetSymbolAddress((void**)&pbq2, g_bnsq2);
        cudaFuncSetAttribute(k_gemm<false>, cudaFuncAttributeMaxDynamicSharedMemorySize,
                             2 * 128 * 128 * sizeof(float));
        cudaFuncSetAttribute(k_gemm<true>, cudaFuncAttributeMaxDynamicSharedMemorySize,
                             2 * 128 * 128 * sizeof(float));
        configured = true;
    }

    float inv_n = 1.f / (float)n;
    int nb_node = (n + 255) / 256;
    int nb_edge = (E + 255) / 256;
    int nb_gemm = (n + 127) / 128;
    int nb_attn = 592;
    int nwarps  = nb_attn * 8;
    int B_scan  = (n + SCAN_CHUNK - 1) / SCAN_CHUNK;
    size_t gsmem = 2 * 128 * 128 * sizeof(float);

    // zero + CSR build
    k_zero<<<nb_node, 256>>>(n);
    k_hist<<<nb_edge, 256>>>(edst, E);
    k_scan1<<<B_scan, SCAN_CHUNK>>>(n);
    k_scan2<<<1, 128>>>(B_scan);
    k_scan3<<<(n + 256) / 256, 256>>>(n);
    k_scatter<<<nb_edge, 256>>>(esrc, edst, E);

    // ---- layer 1 ----
    k_gemm<false><<<nb_gemm, 256, gsmem>>>(x, W1, nullptr, nullptr, as1, ad1, phh, n);
    k_attn<1><<<nb_attn, 256>>>(phh, b1, pbs1, pbq1, n, nwarps);
    k_bnprep<<<1, CH>>>(g1, be1, pbs1, pbq1, psc1, psh1, CH, inv_n);

    // ---- layer 2 (BN+ELU of layer1 fused into GEMM load) ----
    k_gemm<true><<<nb_gemm, 256, gsmem>>>(pacc, W2, psc1, psh1, as2, ad2, phh, n);
    k_attn<2><<<nb_attn, 256>>>(phh, b2, pbs2, pbq2, n, nwarps);
    k_bnprep<<<1, FEAT>>>(g2, be2, pbs2, pbq2, psc2, psh2, FEAT, inv_n);

    // ---- pool (BN+ELU fused) + linear ----
    k_pool<<<nb_node, 256>>>(bat, n);
    k_final<<<(G * 2 + 255) / 256, 256>>>(Wl, bl, out, G);
}